// round 11
// baseline (speedup 1.0000x reference)
#include <cuda_runtime.h>
#include <cuda_bf16.h>
#include <cstdint>
#include <cstddef>

#define QL      64
#define BSZ     8
#define CACHE_L 64
#define CACHE_N 512
#define NHID    1024
#define TOPK    4

#define ATT_ELEMS (QL * BSZ * CACHE_N)   // 262144
#define IDX_ELEMS (TOPK * QL * BSZ)      // 2048
#define NITEM2    (CACHE_N / 4 * BSZ)    // 1024 items: (4-slot group, b)
#define GRID_P    148                    // persistent, 1 CTA/SM

#define NTHR      512                    // 16 warps

// Q hi/lo bf16 scratch, layout [b][i][h]
__device__ __align__(16) __nv_bfloat16 g_qh[BSZ * QL * NHID];
__device__ __align__(16) __nv_bfloat16 g_ql[BSZ * QL * NHID];
// monotonic ticket barrier (never reset -> graph-replay safe)
__device__ unsigned int g_bar = 0;

// ---------------------------------------------------------------------------
__device__ __forceinline__ uint32_t smem_u32(const void* p) {
    uint32_t a;
    asm("{ .reg .u64 t; cvta.to.shared.u64 t, %1; cvt.u32.u64 %0, t; }"
        : "=r"(a) : "l"(p));
    return a;
}
__device__ __forceinline__ void cp_async16(uint32_t dst, const void* src) {
    asm volatile("cp.async.cg.shared.global [%0], [%1], 16;"
                 :: "r"(dst), "l"(src) : "memory");
}
__device__ __forceinline__ void cp_commit() {
    asm volatile("cp.async.commit_group;" ::: "memory");
}
template <int N>
__device__ __forceinline__ void cp_wait() {
    asm volatile("cp.async.wait_group %0;" :: "n"(N) : "memory");
}
__device__ __forceinline__ void ldm_x4(uint32_t& r0, uint32_t& r1,
                                       uint32_t& r2, uint32_t& r3, uint32_t a) {
    asm volatile("ldmatrix.sync.aligned.m8n8.x4.shared.b16 {%0,%1,%2,%3}, [%4];"
                 : "=r"(r0), "=r"(r1), "=r"(r2), "=r"(r3) : "r"(a));
}
__device__ __forceinline__ void mma16816(float* c, const uint32_t* a,
                                         const uint32_t* b) {
    asm volatile(
        "mma.sync.aligned.m16n8k16.row.col.f32.bf16.bf16.f32 "
        "{%0,%1,%2,%3}, {%4,%5,%6,%7}, {%8,%9}, {%0,%1,%2,%3};"
        : "+f"(c[0]), "+f"(c[1]), "+f"(c[2]), "+f"(c[3])
        : "r"(a[0]), "r"(a[1]), "r"(a[2]), "r"(a[3]), "r"(b[0]), "r"(b[1]));
}

// device-wide barrier for a co-resident 148-CTA grid
__device__ __forceinline__ void gbar() {
    __syncthreads();
    if (threadIdx.x == 0) {
        __threadfence();
        unsigned t = atomicAdd(&g_bar, 1u);
        unsigned target = (t / GRID_P + 1u) * GRID_P;
        while (*(volatile unsigned*)&g_bar < target) { }
        __threadfence();
    }
    __syncthreads();
}

// ---------------------------------------------------------------------------
// Fully fused persistent kernel (512 threads, 16 warps):
//   phase 1: qprep
//   phase 2: split-bf16 3-term GEMM, M=256/CTA, warp grid 8m x 2n (32x32)
//   phase 3: softmax + top-4
// ---------------------------------------------------------------------------
#define A_STAGE 65536                  // 256 rows x 256B (64 fp32)
#define B_BASE  (2 * A_STAGE)          // 131072
#define B_STAGE 16384                  // hi 8KB + lo 8KB (64 rows x 128B)
#define SRED_OFF (B_BASE + 2 * B_STAGE)        // 163840
#define SMEM_TOTAL (SRED_OFF + 2048)           // 165888

__global__ void __launch_bounds__(NTHR, 1)
cache_fused_kernel(const float* __restrict__ query,
                   const float* __restrict__ keys,
                   float* __restrict__ out, int write_idx) {
    extern __shared__ char smem[];
    const uint32_t sbase = smem_u32(smem);
    const int tid  = threadIdx.x;
    const int w    = tid >> 5;
    const int lane = tid & 31;
    const int bid  = blockIdx.x;

    // ================= phase 1: qprep ==================
    {
        const int NG = (BSZ * QL * NHID) / 4;        // 131072 granules
        #pragma unroll
        for (int r = 0; r < 2; r++) {
            int g = bid * NTHR + tid + r * (GRID_P * NTHR);
            if (g < NG) {
                int idx = g * 4;
                float4 f = *(const float4*)(query + idx);
                int i  = idx >> 13;
                int bq = (idx >> 10) & 7;
                int hh = idx & 1023;
                int o = (bq * QL + i) * NHID + hh;
                uint32_t bx = __float_as_uint(f.x), by = __float_as_uint(f.y);
                uint32_t bz = __float_as_uint(f.z), bw = __float_as_uint(f.w);
                uint2 hi;
                hi.x = __byte_perm(bx, by, 0x7632);
                hi.y = __byte_perm(bz, bw, 0x7632);
                float r0 = f.x - __uint_as_float(bx & 0xffff0000u);
                float r1 = f.y - __uint_as_float(by & 0xffff0000u);
                float r2 = f.z - __uint_as_float(bz & 0xffff0000u);
                float r3 = f.w - __uint_as_float(bw & 0xffff0000u);
                uint2 lo;
                asm("cvt.rn.bf16x2.f32 %0, %1, %2;" : "=r"(lo.x) : "f"(r1), "f"(r0));
                asm("cvt.rn.bf16x2.f32 %0, %1, %2;" : "=r"(lo.y) : "f"(r3), "f"(r2));
                *(uint2*)(g_qh + o) = hi;
                *(uint2*)(g_ql + o) = lo;
            }
        }
    }
    gbar();

    // ================= phase 2: GEMM ==================
    const int wm = w >> 1;             // m-block 0..7 (rows 32*wm..)
    const int wn = w & 1;              // n-block 0..1 (cols 32*wn..)

    // A staging: thread -> row (tid>>1) of 256, half (tid&1), 8 granules
    const int arow = tid >> 1;
    const int ah2  = tid & 1;
    const size_t aoffR = (size_t)(arow & 63) * NHID + ah2 * 32;
    const int aslot = arow >> 6;       // 0..3 within 4-slot group
    const uint32_t dstA0 = sbase + (uint32_t)(arow * 256)
                         + (uint32_t)(((ah2 * 128) ) ^ ((arow & 7) << 5));

    // B staging (K=64 chunks): 512 threads, 2 granules each
    //   granule id gB = tid (0..511): half = gB>>8, row = (gB>>3)&31 (+32 alt),
    // Simpler: reuse R5 mapping with first 256 threads doing j=0,1 and
    // second 256 doing j=2,3.
    const int bt    = tid & 255;
    const int bkb   = (bt & 7) * 16;
    const int brow0 = bt >> 3;                   // 0..31
    const size_t boff = (size_t)brow0 * NHID + (bt & 7) * 8;
    const int bjlo  = (tid >> 8) * 2;            // 0 or 2

    // B ldmatrix lane pieces
    const int lt    = lane >> 3;
    const int lrow  = ((lt & 2) << 2) + (lane & 7);
    const int lkoff = (lt & 1) << 3;

    // A fragment pieces: warp wm owns rows [32wm, 32wm+32)
    const int afr = (lane >> 2);
    const int afk = (lane & 3) << 1;

    const int nit = (NITEM2 - 1 - bid) / GRID_P + 1;
    const int VCN = nit * 16;

    auto stage = [&](int vc) {
        int il = vc >> 4;
        int g  = bid + GRID_P * il;
        if (g >= NITEM2) return;
        int kc = vc & 15;
        int st = vc & 1;
        int p4 = g & 127;
        int bb = g >> 7;
        // A: 256 rows x 64 fp32
        const float* sA = keys
            + ((size_t)(p4 * 4 + aslot) * BSZ + bb) * (CACHE_L * NHID)
            + aoffR + (size_t)kc * 64;
        uint32_t dA = dstA0 + st * A_STAGE;
        #pragma unroll
        for (int j = 0; j < 8; j++)
            cp_async16(dA ^ (uint32_t)(j * 16), sA + j * 4);
        // B: bf16 hi/lo, 64 rows x 64 cols; each thread 2 granules
        uint32_t dBb = sbase + B_BASE + st * B_STAGE;
        size_t bo = (size_t)bb * (QL * NHID) + boff + (size_t)kc * 64;
        #pragma unroll
        for (int jj = 0; jj < 2; jj++) {
            int j = bjlo + jj;
            int half = j >> 1;
            int row  = brow0 + (j & 1) * 32;
            const __nv_bfloat16* s = (half ? g_ql : g_qh)
                + bo + (size_t)(j & 1) * 32 * NHID;
            uint32_t d = dBb + half * 8192
                       + (uint32_t)(row * 128 + (bkb ^ ((row & 7) << 4)));
            cp_async16(d, s);
        }
    };

    float acc[2][4][4];

    stage(0); cp_commit();
    stage(1); cp_commit();

    #pragma unroll 1
    for (int vc = 0; vc < VCN; vc++) {
        cp_wait<1>();
        __syncthreads();

        const int kc = vc & 15;
        if (kc == 0) {
            #pragma unroll
            for (int mt = 0; mt < 2; mt++)
                #pragma unroll
                for (int nt = 0; nt < 4; nt++)
                    #pragma unroll
                    for (int c = 0; c < 4; c++) acc[mt][nt][c] = 0.0f;
        }

        const uint32_t bufB = sbase + B_BASE + (vc & 1) * B_STAGE;
        const char* baseA = smem + (vc & 1) * A_STAGE;

        #pragma unroll
        for (int ks2 = 0; ks2 < 4; ks2++) {
            // B fragments (hi + lo), this warp's 32-col half: 4 n-tiles
            uint32_t bh[4][2], bl[4][2];
            #pragma unroll
            for (int np = 0; np < 2; np++) {
                int row = wn * 32 + 16 * np + lrow;
                uint32_t kb = (uint32_t)((ks2 * 16 + lkoff) * 2);
                uint32_t swo = (uint32_t)(row * 128 + (kb ^ ((row & 7) << 4)));
                ldm_x4(bh[2 * np][0], bh[2 * np][1],
                       bh[2 * np + 1][0], bh[2 * np + 1][1], bufB + swo);
                ldm_x4(bl[2 * np][0], bl[2 * np][1],
                       bl[2 * np + 1][0], bl[2 * np + 1][1],
                       bufB + 8192 + swo);
            }

            #pragma unroll
            for (int mt = 0; mt < 2; mt++) {
                // A fragment: LDS fp32 once, convert hi/lo in-register
                uint32_t ah[4], al[4];
                {
                    const int R = wm * 32 + mt * 16 + afr;
                    const int kidx = ks2 * 16 + afk;
                    float2 f0 = *(const float2*)(baseA
                        + R * 256 + ((kidx * 4) ^ ((R & 7) << 5)));
                    float2 f1 = *(const float2*)(baseA
                        + (R + 8) * 256 + ((kidx * 4) ^ (((R + 8) & 7) << 5)));
                    float2 f2 = *(const float2*)(baseA
                        + R * 256 + (((kidx + 8) * 4) ^ ((R & 7) << 5)));
                    float2 f3 = *(const float2*)(baseA
                        + (R + 8) * 256 + (((kidx + 8) * 4) ^ (((R + 8) & 7) << 5)));
                    float2 fs[4] = {f0, f1, f2, f3};
                    #pragma unroll
                    for (int j = 0; j < 4; j++) {
                        uint32_t bx = __float_as_uint(fs[j].x);
                        uint32_t by = __float_as_uint(fs[j].y);
                        ah[j] = __byte_perm(bx, by, 0x7632);
                        float rx = fs[j].x - __uint_as_float(bx & 0xffff0000u);
                        float ry = fs[j].y - __uint_as_float(by & 0xffff0000u);
                        asm("cvt.rn.bf16x2.f32 %0, %1, %2;"
                            : "=r"(al[j]) : "f"(ry), "f"(rx));
                    }
                }
                #pragma unroll
                for (int nt = 0; nt < 4; nt++) {
                    mma16816(acc[mt][nt], ah, bh[nt]);
                    mma16816(acc[mt][nt], ah, bl[nt]);
                    mma16816(acc[mt][nt], al, bh[nt]);
                }
            }
        }
        __syncthreads();

        stage(vc + 2);
        cp_commit();

        // ---- item epilogue: max over tokens -> raw logits ----
        if (kc == 15) {
            const int g  = bid + GRID_P * (vc >> 4);
            const int n0 = (g & 127) * 4;
            const int bb = g >> 7;

            // warp covers 32 token-rows of one slot-half; max over them
            float vmax[4][2];
            #pragma unroll
            for (int nt = 0; nt < 4; nt++) {
                float v0 = fmaxf(fmaxf(acc[0][nt][0], acc[0][nt][2]),
                                 fmaxf(acc[1][nt][0], acc[1][nt][2]));
                float v1 = fmaxf(fmaxf(acc[0][nt][1], acc[0][nt][3]),
                                 fmaxf(acc[1][nt][1], acc[1][nt][3]));
                #pragma unroll
                for (int o = 4; o < 32; o <<= 1) {
                    v0 = fmaxf(v0, __shfl_xor_sync(0xffffffffu, v0, o));
                    v1 = fmaxf(v1, __shfl_xor_sync(0xffffffffu, v1, o));
                }
                vmax[nt][0] = v0; vmax[nt][1] = v1;
            }

            float* sred = (float*)(smem + SRED_OFF);   // 16 warps x 32 cols
            if (lane < 4) {
                #pragma unroll
                for (int nt = 0; nt < 4; nt++) {
                    sred[w * 32 + 8 * nt + 2 * lane]     = vmax[nt][0];
                    sred[w * 32 + 8 * nt + 2 * lane + 1] = vmax[nt][1];
                }
            }
            __syncthreads();

            // 256 threads: (slot, query) = (tid>>6, tid&63)
            if (tid < 256) {
                int i   = tid & 63;
                int sl  = tid >> 6;          // 0..3
                int wnq = i >> 5;            // n-block of this query
                int c   = i & 31;
                float v = fmaxf(sred[(4 * sl + wnq) * 32 + c],
                                sred[(4 * sl + 2 + wnq) * 32 + c]);
                out[(size_t)i * (BSZ * CACHE_N) + (size_t)bb * CACHE_N
                    + n0 + sl] = v;
            }
        }
    }

    gbar();

    // ================= phase 3: softmax + top-4 ==================
    {
        const int gid = bid * 16 + w;       // 0..2367
        if (gid < QL * BSZ) {
            float* p = out + (size_t)gid * CACHE_N;
            float v[16];
            float m = -1e30f;
            #pragma unroll
            for (int j = 0; j < 16; j++) {
                v[j] = p[lane + 32 * j] * 0.03125f;   // THETA/sqrt(NHID)
                m = fmaxf(m, v[j]);
            }
            #pragma unroll
            for (int o = 16; o > 0; o >>= 1)
                m = fmaxf(m, __shfl_xor_sync(0xffffffffu, m, o));
            float sum = 0.0f;
            #pragma unroll
            for (int j = 0; j < 16; j++) { v[j] = expf(v[j] - m); sum += v[j]; }
            #pragma unroll
            for (int o = 16; o > 0; o >>= 1)
                sum += __shfl_xor_sync(0xffffffffu, sum, o);
            float inv = 1.0f / sum;
            #pragma unroll
            for (int j = 0; j < 16; j++) {
                v[j] *= inv;
                p[lane + 32 * j] = v[j];
            }
            if (write_idx) {
                float* oidx = out + ATT_ELEMS;
                #pragma unroll 1
                for (int k = 0; k < TOPK; k++) {
                    float bv = -1.0f; int bi = 0;
                    #pragma unroll
                    for (int j = 0; j < 16; j++) {
                        int ii = lane + 32 * j;
                        if (v[j] > bv) { bv = v[j]; bi = ii; }
                    }
                    #pragma unroll
                    for (int o = 16; o > 0; o >>= 1) {
                        float ov = __shfl_xor_sync(0xffffffffu, bv, o);
                        int   oi = __shfl_xor_sync(0xffffffffu, bi, o);
                        if (ov > bv || (ov == bv && oi < bi)) { bv = ov; bi = oi; }
                    }
                    if (lane == 0) oidx[k * (QL * BSZ) + gid] = (float)bi;
                    if ((bi & 31) == lane) v[bi >> 5] = -1.0f;
                }
            }
        }
    }
}

// ---------------------------------------------------------------------------
extern "C" void kernel_launch(void* const* d_in, const int* in_sizes, int n_in,
                              void* d_out, int out_size) {
    const float* a0 = (const float*)d_in[0];
    const float* a1 = (const float*)d_in[1];
    const float* query = a0;
    const float* keys  = a1;
    if (in_sizes[0] != QL * BSZ * NHID) { query = a1; keys = a0; }

    float* out = (float*)d_out;
    int write_idx = (out_size >= ATT_ELEMS + IDX_ELEMS) ? 1 : 0;

    cudaFuncSetAttribute(cache_fused_kernel,
                         cudaFuncAttributeMaxDynamicSharedMemorySize, SMEM_TOTAL);
    cache_fused_kernel<<<GRID_P, NTHR, SMEM_TOTAL>>>(query, keys, out, write_idx);
}

// round 12
// speedup vs baseline: 1.9490x; 1.9490x over previous
#include <cuda_runtime.h>
#include <cuda_bf16.h>
#include <cstdint>
#include <cstddef>

#define QL      64
#define BSZ     8
#define CACHE_L 64
#define CACHE_N 512
#define NHID    1024
#define TOPK    4

#define NPAIRS    (CACHE_N / 2)
#define ATT_ELEMS (QL * BSZ * CACHE_N)   // 262144
#define IDX_ELEMS (TOPK * QL * BSZ)      // 2048

// Q hi/lo bf16 scratch, layout [b][i][h]
__device__ __align__(16) __nv_bfloat16 g_qh[BSZ * QL * NHID];
__device__ __align__(16) __nv_bfloat16 g_ql[BSZ * QL * NHID];

// ---------------------------------------------------------------------------
__device__ __forceinline__ uint32_t smem_u32(const void* p) {
    uint32_t a;
    asm("{ .reg .u64 t; cvta.to.shared.u64 t, %1; cvt.u32.u64 %0, t; }"
        : "=r"(a) : "l"(p));
    return a;
}

__device__ __forceinline__ void cp_async16(uint32_t dst, const void* src) {
    asm volatile("cp.async.cg.shared.global [%0], [%1], 16;"
                 :: "r"(dst), "l"(src) : "memory");
}
__device__ __forceinline__ void cp_commit() {
    asm volatile("cp.async.commit_group;" ::: "memory");
}
template <int N>
__device__ __forceinline__ void cp_wait() {
    asm volatile("cp.async.wait_group %0;" :: "n"(N) : "memory");
}

__device__ __forceinline__ void ldm_x4(uint32_t& r0, uint32_t& r1,
                                       uint32_t& r2, uint32_t& r3, uint32_t a) {
    asm volatile("ldmatrix.sync.aligned.m8n8.x4.shared.b16 {%0,%1,%2,%3}, [%4];"
                 : "=r"(r0), "=r"(r1), "=r"(r2), "=r"(r3) : "r"(a));
}

__device__ __forceinline__ void mma16816(float* c, const uint32_t* a,
                                         const uint32_t* b) {
    asm volatile(
        "mma.sync.aligned.m16n8k16.row.col.f32.bf16.bf16.f32 "
        "{%0,%1,%2,%3}, {%4,%5,%6,%7}, {%8,%9}, {%0,%1,%2,%3};"
        : "+f"(c[0]), "+f"(c[1]), "+f"(c[2]), "+f"(c[3])
        : "r"(a[0]), "r"(a[1]), "r"(a[2]), "r"(a[3]), "r"(b[0]), "r"(b[1]));
}

// ---------------------------------------------------------------------------
// Pass 0: split query fp32 -> (hi truncated bf16, lo round-nearest bf16)
// 4 elements per thread, vectorized I/O. (R8 fast version, measured 4.6us)
// ---------------------------------------------------------------------------
__global__ void qprep_kernel(const float* __restrict__ query) {
    int t = blockIdx.x * 256 + threadIdx.x;     // 0..131071
    int idx = t * 4;
    float4 f = *(const float4*)(query + idx);
    int i  = idx >> 13;
    int b  = (idx >> 10) & 7;
    int hh = idx & 1023;
    int o = (b * QL + i) * NHID + hh;

    uint32_t bx = __float_as_uint(f.x), by = __float_as_uint(f.y);
    uint32_t bz = __float_as_uint(f.z), bw = __float_as_uint(f.w);
    uint2 hi;
    hi.x = __byte_perm(bx, by, 0x7632);
    hi.y = __byte_perm(bz, bw, 0x7632);
    float r0 = f.x - __uint_as_float(bx & 0xffff0000u);
    float r1 = f.y - __uint_as_float(by & 0xffff0000u);
    float r2 = f.z - __uint_as_float(bz & 0xffff0000u);
    float r3 = f.w - __uint_as_float(bw & 0xffff0000u);
    uint2 lo;
    asm("cvt.rn.bf16x2.f32 %0, %1, %2;" : "=r"(lo.x) : "f"(r1), "f"(r0));
    asm("cvt.rn.bf16x2.f32 %0, %1, %2;" : "=r"(lo.y) : "f"(r3), "f"(r2));
    *(uint2*)(g_qh + o) = hi;
    *(uint2*)(g_ql + o) = lo;
}

// ---------------------------------------------------------------------------
// Pass 1: split-bf16 3-term GEMM (R5 VERBATIM — measured best GEMM).
//   CTA: M=128 (2 slots x 64 tokens), N=64, K=1024 in 16 chunks of 64.
//   8 warps, warp tile 16 x 64 (A-dup=1). A cp.async fp32 -> smem (2-stage),
//   converted in-register per fragment. B bf16 hi/lo cp.async (2-stage).
// ---------------------------------------------------------------------------
#define A_STAGE 32768                  // 128 rows x 256B (64 fp32)
#define B_STAGE 16384                  // hi 8KB + lo 8KB (64 rows x 128B)
#define B_BASE  (2 * A_STAGE)          // 65536
#define SMEM_TOTAL (B_BASE + 2 * B_STAGE)   // 98304

__global__ void __launch_bounds__(256, 2)
cache_gemm_kernel(const float* __restrict__ keys, float* __restrict__ out) {
    extern __shared__ char smem[];
    const uint32_t sbase = smem_u32(smem);
    const int tid  = threadIdx.x;
    const int w    = tid >> 5;
    const int lane = tid & 31;
    const int b    = blockIdx.y;
    const int n0   = blockIdx.x * 2;

    // ---- A cp.async mapping: 8 granules of 16B per thread per chunk
    const int arow0 = tid >> 4;                   // 0..15
    const int akb   = (tid & 15) * 16;
    const float* srcA0 = keys
        + ((size_t)n0 * BSZ + b) * (CACHE_L * NHID)
        + (size_t)arow0 * NHID + (tid & 15) * 4;
    const uint32_t dstA0 = sbase + (uint32_t)(arow0 * 256
                         + (akb ^ ((arow0 & 7) << 5)));

    // ---- B cp.async mapping: 4 granules of 16B per thread per chunk
    const int bkb   = (tid & 7) * 16;
    const int brow0 = tid >> 3;                   // 0..31
    const size_t srcBoff = ((size_t)b * QL + brow0) * NHID + (tid & 7) * 8;

    // ---- ldmatrix per-lane pieces (B fragments)
    const int lt    = lane >> 3;
    const int lrow  = ((lt & 2) << 2) + (lane & 7);
    const int lkoff = (lt & 1) << 3;

    // ---- A fragment LDS pieces: warp w owns rows [16w, 16w+16)
    const int afr = (lane >> 2);
    const int afk = (lane & 3) << 1;

    float acc[8][4];
    #pragma unroll
    for (int nt = 0; nt < 8; nt++)
        #pragma unroll
        for (int c = 0; c < 4; c++) acc[nt][c] = 0.0f;

    // ---- prologue: stage chunks 0 and 1
    #pragma unroll 1
    for (int pk = 0; pk < 2; pk++) {
        uint32_t dA = dstA0 + pk * A_STAGE;
        const float* sA = srcA0 + pk * 64;
        #pragma unroll
        for (int j = 0; j < 8; j++) {
            const float* s = sA + j * 16 * NHID
                           + ((j >= 4) ? (7 * CACHE_L * NHID) : 0);
            cp_async16(dA + j * 4096, s);
        }
        uint32_t dBb = sbase + B_BASE + pk * B_STAGE;
        #pragma unroll
        for (int j = 0; j < 4; j++) {
            int half = j >> 1;
            int row  = brow0 + (j & 1) * 32;
            const __nv_bfloat16* s = (half ? g_ql : g_qh)
                + srcBoff + (size_t)(j & 1) * 32 * NHID + pk * 64;
            uint32_t d = dBb + half * 8192
                       + (uint32_t)(row * 128 + (bkb ^ ((row & 7) << 4)));
            cp_async16(d, s);
        }
        cp_commit();
    }

    #pragma unroll 1
    for (int kc = 0; kc < 16; kc++) {
        cp_wait<1>();
        __syncthreads();

        const uint32_t bufB = sbase + B_BASE + (kc & 1) * B_STAGE;

        #pragma unroll
        for (int ks2 = 0; ks2 < 4; ks2++) {
            // ---- B fragments via ldmatrix (hi + lo), 8 n-tiles
            uint32_t bh[8][2], bl[8][2];
            #pragma unroll
            for (int np = 0; np < 4; np++) {
                int row = 16 * np + lrow;
                uint32_t kb = (uint32_t)((ks2 * 16 + lkoff) * 2);
                uint32_t swo = (uint32_t)(row * 128 + (kb ^ ((row & 7) << 4)));
                ldm_x4(bh[2 * np][0], bh[2 * np][1],
                       bh[2 * np + 1][0], bh[2 * np + 1][1], bufB + swo);
                ldm_x4(bl[2 * np][0], bl[2 * np][1],
                       bl[2 * np + 1][0], bl[2 * np + 1][1],
                       bufB + 8192 + swo);
            }

            // ---- A fragment: LDS fp32 once, convert hi/lo in-register
            uint32_t ah[4], al[4];
            {
                const int R = w * 16 + afr;
                const int kidx = ks2 * 16 + afk;
                const char* base = smem + (kc & 1) * A_STAGE;
                float2 f0 = *(const float2*)(base
                    + R * 256 + ((kidx * 4) ^ ((R & 7) << 5)));
                float2 f1 = *(const float2*)(base
                    + (R + 8) * 256 + ((kidx * 4) ^ (((R + 8) & 7) << 5)));
                float2 f2 = *(const float2*)(base
                    + R * 256 + (((kidx + 8) * 4) ^ ((R & 7) << 5)));
                float2 f3 = *(const float2*)(base
                    + (R + 8) * 256 + (((kidx + 8) * 4) ^ (((R + 8) & 7) << 5)));
                float2 fs[4] = {f0, f1, f2, f3};
                #pragma unroll
                for (int j = 0; j < 4; j++) {
                    uint32_t bx = __float_as_uint(fs[j].x);
                    uint32_t by = __float_as_uint(fs[j].y);
                    ah[j] = __byte_perm(bx, by, 0x7632);
                    float rx = fs[j].x - __uint_as_float(bx & 0xffff0000u);
                    float ry = fs[j].y - __uint_as_float(by & 0xffff0000u);
                    asm("cvt.rn.bf16x2.f32 %0, %1, %2;"
                        : "=r"(al[j]) : "f"(ry), "f"(rx));
                }
            }

            // ---- 24 HMMA: Ah*Bh + Ah*Bl + Al*Bh
            #pragma unroll
            for (int nt = 0; nt < 8; nt++) {
                mma16816(acc[nt], ah, bh[nt]);
                mma16816(acc[nt], ah, bl[nt]);
                mma16816(acc[nt], al, bh[nt]);
            }
        }
        __syncthreads();

        // ---- stage chunk kc+2 into the buffer just freed
        if (kc + 2 < 16) {
            uint32_t dA = dstA0 + (kc & 1) * A_STAGE;
            const float* sA = srcA0 + (kc + 2) * 64;
            #pragma unroll
            for (int j = 0; j < 8; j++) {
                const float* s = sA + j * 16 * NHID
                               + ((j >= 4) ? (7 * CACHE_L * NHID) : 0);
                cp_async16(dA + j * 4096, s);
            }
            uint32_t dBb = sbase + B_BASE + (kc & 1) * B_STAGE;
            #pragma unroll
            for (int j = 0; j < 4; j++) {
                int half = j >> 1;
                int row  = brow0 + (j & 1) * 32;
                const __nv_bfloat16* s = (half ? g_ql : g_qh)
                    + srcBoff + (size_t)(j & 1) * 32 * NHID + (kc + 2) * 64;
                uint32_t d = dBb + half * 8192
                           + (uint32_t)(row * 128 + (bkb ^ ((row & 7) << 4)));
                cp_async16(d, s);
            }
        }
        cp_commit();   // unconditional: keeps group accounting uniform
    }

    // ---- epilogue: max over this warp's 16 token rows, per query column ----
    float vmax[8][2];
    #pragma unroll
    for (int nt = 0; nt < 8; nt++) {
        float v0 = fmaxf(acc[nt][0], acc[nt][2]);
        float v1 = fmaxf(acc[nt][1], acc[nt][3]);
        #pragma unroll
        for (int o = 4; o < 32; o <<= 1) {
            v0 = fmaxf(v0, __shfl_xor_sync(0xffffffffu, v0, o));
            v1 = fmaxf(v1, __shfl_xor_sync(0xffffffffu, v1, o));
        }
        vmax[nt][0] = v0; vmax[nt][1] = v1;
    }

    float* sred = (float*)smem;   // 8 warps x 64 cols
    if (lane < 4) {
        #pragma unroll
        for (int nt = 0; nt < 8; nt++) {
            sred[w * 64 + 8 * nt + 2 * lane]     = vmax[nt][0];
            sred[w * 64 + 8 * nt + 2 * lane + 1] = vmax[nt][1];
        }
    }
    __syncthreads();

    if (tid < 128) {
        int i  = tid & 63;          // query index
        int sl = tid >> 6;          // slot within pair (warps 0-3 / 4-7)
        float v = fmaxf(fmaxf(sred[(4 * sl + 0) * 64 + i],
                              sred[(4 * sl + 1) * 64 + i]),
                        fmaxf(sred[(4 * sl + 2) * 64 + i],
                              sred[(4 * sl + 3) * 64 + i]));
        out[(size_t)i * (BSZ * CACHE_N) + (size_t)b * CACHE_N + n0 + sl] = v;
    }
}

// ---------------------------------------------------------------------------
// Pass 2: softmax over N=512 (scale 1/32) in-place + top-4 indices.
// One warp per (ql,b) row; no __syncthreads. (R8 fast version)
// ---------------------------------------------------------------------------
__global__ void softmax_topk_kernel(float* __restrict__ out, int write_idx) {
    const int row  = blockIdx.x * 8 + (threadIdx.x >> 5);
    const int lane = threadIdx.x & 31;
    float* p = out + (size_t)row * CACHE_N;

    float v[16];
    float m = -1e30f;
    #pragma unroll
    for (int j = 0; j < 16; j++) {
        v[j] = p[lane + 32 * j] * 0.03125f;   // THETA / sqrt(NHID)
        m = fmaxf(m, v[j]);
    }
    #pragma unroll
    for (int o = 16; o > 0; o >>= 1)
        m = fmaxf(m, __shfl_xor_sync(0xffffffffu, m, o));

    float sum = 0.0f;
    #pragma unroll
    for (int j = 0; j < 16; j++) { v[j] = expf(v[j] - m); sum += v[j]; }
    #pragma unroll
    for (int o = 16; o > 0; o >>= 1)
        sum += __shfl_xor_sync(0xffffffffu, sum, o);

    float inv = 1.0f / sum;
    #pragma unroll
    for (int j = 0; j < 16; j++) {
        v[j] *= inv;
        p[lane + 32 * j] = v[j];
    }

    if (write_idx) {
        float* oidx = out + ATT_ELEMS;
        #pragma unroll 1
        for (int k = 0; k < TOPK; k++) {
            float bv = -1.0f; int bi = 0;
            #pragma unroll
            for (int j = 0; j < 16; j++) {
                int ii = lane + 32 * j;
                if (v[j] > bv) { bv = v[j]; bi = ii; }   // ascending: tie->lower
            }
            #pragma unroll
            for (int o = 16; o > 0; o >>= 1) {
                float ov = __shfl_xor_sync(0xffffffffu, bv, o);
                int   oi = __shfl_xor_sync(0xffffffffu, bi, o);
                if (ov > bv || (ov == bv && oi < bi)) { bv = ov; bi = oi; }
            }
            if (lane == 0) oidx[k * (QL * BSZ) + row] = (float)bi;
            if ((bi & 31) == lane) v[bi >> 5] = -1.0f;   // remove winner
        }
    }
}

// ---------------------------------------------------------------------------
extern "C" void kernel_launch(void* const* d_in, const int* in_sizes, int n_in,
                              void* d_out, int out_size) {
    const float* a0 = (const float*)d_in[0];
    const float* a1 = (const float*)d_in[1];
    const float* query = a0;
    const float* keys  = a1;
    if (in_sizes[0] != QL * BSZ * NHID) { query = a1; keys = a0; }

    float* out = (float*)d_out;

    qprep_kernel<<<(BSZ * QL * NHID) / 1024, 256>>>(query);

    cudaFuncSetAttribute(cache_gemm_kernel,
                         cudaFuncAttributeMaxDynamicSharedMemorySize, SMEM_TOTAL);
    cache_gemm_kernel<<<dim3(NPAIRS, BSZ), 256, SMEM_TOTAL>>>(keys, out);

    int write_idx = (out_size >= ATT_ELEMS + IDX_ELEMS) ? 1 : 0;
    softmax_topk_kernel<<<QL * BSZ / 8, 256>>>(out, write_idx);
}